// round 1
// baseline (speedup 1.0000x reference)
#include <cuda_runtime.h>
#include <cstdint>

// Scratch (allocation-free): projected + pre-scaled MLP activations.
// a' = 0.5*(x@W1_half1 + b1), b' = 0.5*(x@W1_half2), so sigmoid(a+b+b1) =
// 0.5*tanh(a'+b') + 0.5.
__device__ float g_aST[32 * 1024 * 32];  // spatial  @ st_w1[:D]  (+ st_b1)
__device__ float g_bTS[32 * 1024 * 32];  // spatial  @ ts_w1[D:]
__device__ float g_aTS[32 * 64 * 32];    // temporal @ ts_w1[:D]  (+ ts_b1)
__device__ float g_bST[32 * 64 * 32];    // temporal @ st_w1[D:]

__device__ __forceinline__ float tanh_fast(float x) {
    float y;
    asm("tanh.approx.f32 %0, %1;" : "=f"(y) : "f"(x));
    return y;
}

// ---------------------------------------------------------------------------
// Projection kernel: tiny GEMMs (B*(N+T) rows x 32 -> 32), two outputs per row.
// blockIdx.y==0 : spatial rows (32768), blockIdx.y==1 : temporal rows (2048).
// 256 threads = 8 rows x 32 output dims.
// ---------------------------------------------------------------------------
__global__ void proj_kernel(const float* __restrict__ spatial,
                            const float* __restrict__ temporal,
                            const float* __restrict__ st_w1,
                            const float* __restrict__ st_b1,
                            const float* __restrict__ ts_w1,
                            const float* __restrict__ ts_b1) {
    const bool sp = (blockIdx.y == 0);
    if (!sp && blockIdx.x >= 256) return;  // temporal needs only 2048/8 blocks

    __shared__ float WA[32][32];
    __shared__ float WB[32][32];
    __shared__ float bias[32];
    __shared__ float X[8][32];

    const int tid = threadIdx.x;
    // spatial rows:  A = st_w1[:32] (+st_b1),  B = ts_w1[32:]
    // temporal rows: A = ts_w1[:32] (+ts_b1),  B = st_w1[32:]
    const float* wa = sp ? st_w1 : ts_w1;
    const float* wb = sp ? (ts_w1 + 1024) : (st_w1 + 1024);
    const float* ba = sp ? st_b1 : ts_b1;

    for (int i = tid; i < 1024; i += 256) {
        WA[i >> 5][i & 31] = wa[i];
        WB[i >> 5][i & 31] = wb[i];
    }
    if (tid < 32) bias[tid] = ba[tid];

    const int d = tid & 31;
    const int r = tid >> 5;
    const int row = blockIdx.x * 8 + r;  // global row within [B*rows]
    const float* xsrc = sp ? (spatial + (size_t)row * 32)
                           : (temporal + (size_t)row * 32);
    X[r][d] = xsrc[d];
    __syncthreads();

    float accA = 0.f, accB = 0.f;
#pragma unroll
    for (int k = 0; k < 32; k++) {
        const float xv = X[r][k];
        accA = fmaf(xv, WA[k][d], accA);
        accB = fmaf(xv, WB[k][d], accB);
    }
    const float aout = 0.5f * (accA + bias[d]);
    const float bout = 0.5f * accB;
    const size_t o = (size_t)row * 32 + d;
    if (sp) {
        g_aST[o] = aout;
        g_bTS[o] = bout;
    } else {
        g_aTS[o] = aout;
        g_bST[o] = bout;
    }
}

// ---------------------------------------------------------------------------
// Main kernel: one 64x64 output tile per block, 17x17 tiles per batch.
// Tile (ti,tj): ti<16 & tj<16 -> SS gram; ti==16 & tj==16 -> TT gram;
// ti<16 & tj==16 -> ST MLP; ti==16 & tj<16 -> TS MLP.
// 256 threads, each computes a 4x4 register tile.
// ---------------------------------------------------------------------------
__global__ __launch_bounds__(256) void adj_kernel(
    const float* __restrict__ spatial, const float* __restrict__ temporal,
    const float* __restrict__ st_w2, const float* __restrict__ st_b2,
    const float* __restrict__ ts_w2, const float* __restrict__ ts_b2,
    float* __restrict__ out) {
    __shared__ float As[32][68];  // k-major, padded (68*4B multiple of 16B)
    __shared__ float Bs[32][68];
    __shared__ float sw[33];      // [0..31]=0.5*w2, [32]=b2+0.5*sum(w2)

    const int blk = blockIdx.x;
    const int b = blk / 289;
    const int r = blk % 289;
    const int ti = r / 17;
    const int tj = r % 17;
    const int tid = threadIdx.x;

    const bool rowSp = (ti < 16);
    const bool colSp = (tj < 16);
    const bool isGram = (rowSp == colSp);

    const float* Asrc;
    const float* Bsrc;
    const float* w2 = st_w2;
    const float* b2 = st_b2;
    if (isGram) {
        Asrc = rowSp ? (spatial + ((size_t)b * 1024 + ti * 64) * 32)
                     : (temporal + (size_t)b * 64 * 32);
        Bsrc = colSp ? (spatial + ((size_t)b * 1024 + tj * 64) * 32)
                     : (temporal + (size_t)b * 64 * 32);
    } else if (rowSp) {  // ST block
        Asrc = g_aST + ((size_t)b * 1024 + ti * 64) * 32;
        Bsrc = g_bST + (size_t)b * 64 * 32;
        w2 = st_w2;
        b2 = st_b2;
    } else {  // TS block
        Asrc = g_aTS + (size_t)b * 64 * 32;
        Bsrc = g_bTS + ((size_t)b * 1024 + tj * 64) * 32;
        w2 = ts_w2;
        b2 = ts_b2;
    }

    // Load 64x32 row-major tiles, transpose to k-major in smem.
    for (int l = tid; l < 512; l += 256) {
        const int row = l >> 3;
        const int kq = (l & 7) << 2;
        const float4 va = *(const float4*)(Asrc + row * 32 + kq);
        As[kq + 0][row] = va.x;
        As[kq + 1][row] = va.y;
        As[kq + 2][row] = va.z;
        As[kq + 3][row] = va.w;
        const float4 vb = *(const float4*)(Bsrc + row * 32 + kq);
        Bs[kq + 0][row] = vb.x;
        Bs[kq + 1][row] = vb.y;
        Bs[kq + 2][row] = vb.z;
        Bs[kq + 3][row] = vb.w;
    }
    if (!isGram && tid < 32) sw[tid] = 0.5f * w2[tid];
    __syncthreads();
    if (!isGram && tid == 0) {
        float s = b2[0];
#pragma unroll
        for (int k = 0; k < 32; k++) s += sw[k];
        sw[32] = s;
    }
    __syncthreads();

    const int tx = tid & 15;   // j
    const int ty = tid >> 4;   // i
    float acc[4][4];
#pragma unroll
    for (int i = 0; i < 4; i++)
#pragma unroll
        for (int j = 0; j < 4; j++) acc[i][j] = 0.f;

    const float* ap = &As[0][ty * 4];
    const float* bp = &Bs[0][tx * 4];

    if (isGram) {
#pragma unroll
        for (int k = 0; k < 32; k++) {
            const float4 a = *(const float4*)(ap + k * 68);
            const float4 bb = *(const float4*)(bp + k * 68);
            const float av[4] = {a.x, a.y, a.z, a.w};
            const float bv[4] = {bb.x, bb.y, bb.z, bb.w};
#pragma unroll
            for (int i = 0; i < 4; i++)
#pragma unroll
                for (int j = 0; j < 4; j++)
                    acc[i][j] = fmaf(av[i], bv[j], acc[i][j]);
        }
    } else {
#pragma unroll
        for (int k = 0; k < 32; k++) {
            const float4 a = *(const float4*)(ap + k * 68);
            const float4 bb = *(const float4*)(bp + k * 68);
            const float av[4] = {a.x, a.y, a.z, a.w};
            const float bv[4] = {bb.x, bb.y, bb.z, bb.w};
            const float w = sw[k];
#pragma unroll
            for (int i = 0; i < 4; i++)
#pragma unroll
                for (int j = 0; j < 4; j++) {
                    // sigmoid(a+b+b1) = 0.5*tanh(a'+b')+0.5 ; the +0.5*w2 part
                    // is folded into sw[32].
                    const float t = tanh_fast(av[i] + bv[j]);
                    acc[i][j] = fmaf(t, w, acc[i][j]);
                }
        }
        const float c0 = sw[32];
#pragma unroll
        for (int i = 0; i < 4; i++)
#pragma unroll
            for (int j = 0; j < 4; j++) acc[i][j] += c0;
    }

    // Epilogue: tanh(relu(x)), coalesced float4 stores.
    const int gi0 = ti * 64 + ty * 4;
    const int gj0 = tj * 64 + tx * 4;
    float* obase = out + ((size_t)b * 1088 + gi0) * 1088 + gj0;
#pragma unroll
    for (int i = 0; i < 4; i++) {
        float4 v;
        v.x = tanh_fast(fmaxf(acc[i][0], 0.f));
        v.y = tanh_fast(fmaxf(acc[i][1], 0.f));
        v.z = tanh_fast(fmaxf(acc[i][2], 0.f));
        v.w = tanh_fast(fmaxf(acc[i][3], 0.f));
        *(float4*)(obase + (size_t)i * 1088) = v;
    }
}

extern "C" void kernel_launch(void* const* d_in, const int* in_sizes, int n_in,
                              void* d_out, int out_size) {
    const float* spatial = (const float*)d_in[0];   // [32,1024,32]
    const float* temporal = (const float*)d_in[1];  // [32,64,32]
    const float* st_w1 = (const float*)d_in[2];     // [64,32]
    const float* st_b1 = (const float*)d_in[3];     // [32]
    const float* st_w2 = (const float*)d_in[4];     // [32,1]
    const float* st_b2 = (const float*)d_in[5];     // [1]
    const float* ts_w1 = (const float*)d_in[6];
    const float* ts_b1 = (const float*)d_in[7];
    const float* ts_w2 = (const float*)d_in[8];
    const float* ts_b2 = (const float*)d_in[9];
    float* out = (float*)d_out;                     // [32,1088,1088]

    // Projections: 32768 spatial rows (y=0) + 2048 temporal rows (y=1), 8/blk.
    proj_kernel<<<dim3(4096, 2), 256>>>(spatial, temporal, st_w1, st_b1,
                                        ts_w1, ts_b1);
    // 32 batches * 17*17 tiles of 64x64.
    adj_kernel<<<32 * 289, 256>>>(spatial, temporal, st_w2, st_b2, ts_w2,
                                  ts_b2, out);
}